// round 1
// baseline (speedup 1.0000x reference)
#include <cuda_runtime.h>
#include <math.h>

// Problem shape (fixed by the reference)
#define NB   4
#define SEQ  2048
#define DIN  1024
#define DH   1024

// Scratch: __device__ globals (no allocations allowed in kernel_launch)
__device__ float g_Q [(size_t)NB * SEQ * DH];   // 32 MB
__device__ float g_K [(size_t)NB * SEQ * DH];   // 32 MB
__device__ float g_V [(size_t)NB * SEQ * DH];   // 32 MB
__device__ float g_Sc[(size_t)NB * SEQ * SEQ];  // 64 MB

// Tiling
constexpr int BM = 128, BN = 128, BK = 16, TM = 8, TN = 8;
constexpr int NTHREADS = (BM / TM) * (BN / TN);  // 256
constexpr int PAD = 4;  // smem pad: kills 4-way write conflicts, keeps 16B alignment

// ---------------------------------------------------------------------------
// C = alpha * A @ B^T      A:[M,K] row-major, B:[N,K] row-major
// Batched over blockIdx.z with element strides.
// All dims assumed multiples of the tile sizes (true for this problem).
// ---------------------------------------------------------------------------
__global__ __launch_bounds__(NTHREADS)
void gemm_nt_kernel(const float* __restrict__ A, const float* __restrict__ Bm,
                    float* __restrict__ C,
                    int M, int N, int K, float alpha,
                    size_t strideA, size_t strideB, size_t strideC)
{
    const float* Ab = A  + strideA * blockIdx.z;
    const float* Bb = Bm + strideB * blockIdx.z;
    float*       Cb = C  + strideC * blockIdx.z;

    __shared__ float As[BK][BM + PAD];
    __shared__ float Bs[BK][BN + PAD];

    const int tid = threadIdx.x;
    const int bm  = blockIdx.y * BM;
    const int bn  = blockIdx.x * BN;
    const int tx  = tid % (BN / TN);   // 0..15
    const int ty  = tid / (BN / TN);   // 0..15

    // K-contiguous float4 loads, stored transposed into smem
    const int lRow = tid >> 2;         // tid / (BK/4)  -> 0..63
    const int lCol = (tid & 3) * 4;    // 0,4,8,12

    float acc[TM][TN] = {};

    for (int k0 = 0; k0 < K; k0 += BK) {
        #pragma unroll
        for (int i = 0; i < BM; i += 64) {
            float4 v = *reinterpret_cast<const float4*>(
                &Ab[(size_t)(bm + lRow + i) * K + k0 + lCol]);
            As[lCol + 0][lRow + i] = v.x;
            As[lCol + 1][lRow + i] = v.y;
            As[lCol + 2][lRow + i] = v.z;
            As[lCol + 3][lRow + i] = v.w;
        }
        #pragma unroll
        for (int i = 0; i < BN; i += 64) {
            float4 v = *reinterpret_cast<const float4*>(
                &Bb[(size_t)(bn + lRow + i) * K + k0 + lCol]);
            Bs[lCol + 0][lRow + i] = v.x;
            Bs[lCol + 1][lRow + i] = v.y;
            Bs[lCol + 2][lRow + i] = v.z;
            Bs[lCol + 3][lRow + i] = v.w;
        }
        __syncthreads();

        #pragma unroll
        for (int kk = 0; kk < BK; kk++) {
            float ra[TM], rb[TN];
            #pragma unroll
            for (int i = 0; i < TM; i++) ra[i] = As[kk][ty * TM + i];
            #pragma unroll
            for (int j = 0; j < TN; j++) rb[j] = Bs[kk][tx * TN + j];
            #pragma unroll
            for (int i = 0; i < TM; i++)
                #pragma unroll
                for (int j = 0; j < TN; j++)
                    acc[i][j] = fmaf(ra[i], rb[j], acc[i][j]);
        }
        __syncthreads();
    }

    #pragma unroll
    for (int i = 0; i < TM; i++) {
        size_t cBase = (size_t)(bm + ty * TM + i) * N + bn + tx * TN;
        #pragma unroll
        for (int j = 0; j < TN; j += 4) {
            float4 v = make_float4(alpha * acc[i][j + 0], alpha * acc[i][j + 1],
                                   alpha * acc[i][j + 2], alpha * acc[i][j + 3]);
            *reinterpret_cast<float4*>(&Cb[cBase + j]) = v;
        }
    }
}

// ---------------------------------------------------------------------------
// C = A @ B                A:[M,K] row-major, B:[K,N] row-major
// ---------------------------------------------------------------------------
__global__ __launch_bounds__(NTHREADS)
void gemm_nn_kernel(const float* __restrict__ A, const float* __restrict__ Bm,
                    float* __restrict__ C,
                    int M, int N, int K,
                    size_t strideA, size_t strideB, size_t strideC)
{
    const float* Ab = A  + strideA * blockIdx.z;
    const float* Bb = Bm + strideB * blockIdx.z;
    float*       Cb = C  + strideC * blockIdx.z;

    __shared__ float As[BK][BM + PAD];
    __shared__ float Bs[BK][BN + PAD];

    const int tid = threadIdx.x;
    const int bm  = blockIdx.y * BM;
    const int bn  = blockIdx.x * BN;
    const int tx  = tid % (BN / TN);
    const int ty  = tid / (BN / TN);

    // A: same transposed-store pattern as NT kernel
    const int aRow = tid >> 2;
    const int aCol = (tid & 3) * 4;
    // B: direct [BK x BN] float4 loads (N-contiguous)
    const int bRow = tid >> 5;         // 0..7
    const int bCol = (tid & 31) * 4;   // 0..124

    float acc[TM][TN] = {};

    for (int k0 = 0; k0 < K; k0 += BK) {
        #pragma unroll
        for (int i = 0; i < BM; i += 64) {
            float4 v = *reinterpret_cast<const float4*>(
                &Ab[(size_t)(bm + aRow + i) * K + k0 + aCol]);
            As[aCol + 0][aRow + i] = v.x;
            As[aCol + 1][aRow + i] = v.y;
            As[aCol + 2][aRow + i] = v.z;
            As[aCol + 3][aRow + i] = v.w;
        }
        #pragma unroll
        for (int i = 0; i < BK; i += 8) {
            float4 v = *reinterpret_cast<const float4*>(
                &Bb[(size_t)(k0 + bRow + i) * N + bn + bCol]);
            *reinterpret_cast<float4*>(&Bs[bRow + i][bCol]) = v;
        }
        __syncthreads();

        #pragma unroll
        for (int kk = 0; kk < BK; kk++) {
            float ra[TM], rb[TN];
            #pragma unroll
            for (int i = 0; i < TM; i++) ra[i] = As[kk][ty * TM + i];
            #pragma unroll
            for (int j = 0; j < TN; j++) rb[j] = Bs[kk][tx * TN + j];
            #pragma unroll
            for (int i = 0; i < TM; i++)
                #pragma unroll
                for (int j = 0; j < TN; j++)
                    acc[i][j] = fmaf(ra[i], rb[j], acc[i][j]);
        }
        __syncthreads();
    }

    #pragma unroll
    for (int i = 0; i < TM; i++) {
        size_t cBase = (size_t)(bm + ty * TM + i) * N + bn + tx * TN;
        #pragma unroll
        for (int j = 0; j < TN; j += 4) {
            float4 v = make_float4(acc[i][j + 0], acc[i][j + 1],
                                   acc[i][j + 2], acc[i][j + 3]);
            *reinterpret_cast<float4*>(&Cb[cBase + j]) = v;
        }
    }
}

// ---------------------------------------------------------------------------
// In-place row softmax. One block per row of SEQ=2048 floats.
// 256 threads x 8 elements (2x float4), register-resident.
// ---------------------------------------------------------------------------
__global__ __launch_bounds__(256)
void softmax_kernel(float* __restrict__ S)
{
    float* row = S + (size_t)blockIdx.x * SEQ;
    const int tid  = threadIdx.x;
    const int lane = tid & 31;
    const int warp = tid >> 5;

    float4 v0 = reinterpret_cast<float4*>(row)[tid];
    float4 v1 = reinterpret_cast<float4*>(row)[tid + 256];

    __shared__ float red[8];

    // --- max reduce ---
    float m = fmaxf(fmaxf(fmaxf(v0.x, v0.y), fmaxf(v0.z, v0.w)),
                    fmaxf(fmaxf(v1.x, v1.y), fmaxf(v1.z, v1.w)));
    #pragma unroll
    for (int o = 16; o > 0; o >>= 1) m = fmaxf(m, __shfl_xor_sync(0xFFFFFFFFu, m, o));
    if (lane == 0) red[warp] = m;
    __syncthreads();
    m = red[0];
    #pragma unroll
    for (int w = 1; w < 8; w++) m = fmaxf(m, red[w]);
    __syncthreads();

    // --- exp + sum reduce ---
    v0.x = __expf(v0.x - m); v0.y = __expf(v0.y - m);
    v0.z = __expf(v0.z - m); v0.w = __expf(v0.w - m);
    v1.x = __expf(v1.x - m); v1.y = __expf(v1.y - m);
    v1.z = __expf(v1.z - m); v1.w = __expf(v1.w - m);

    float s = (v0.x + v0.y + v0.z + v0.w) + (v1.x + v1.y + v1.z + v1.w);
    #pragma unroll
    for (int o = 16; o > 0; o >>= 1) s += __shfl_xor_sync(0xFFFFFFFFu, s, o);
    if (lane == 0) red[warp] = s;
    __syncthreads();
    s = red[0];
    #pragma unroll
    for (int w = 1; w < 8; w++) s += red[w];

    float inv = 1.0f / s;
    v0.x *= inv; v0.y *= inv; v0.z *= inv; v0.w *= inv;
    v1.x *= inv; v1.y *= inv; v1.z *= inv; v1.w *= inv;

    reinterpret_cast<float4*>(row)[tid]       = v0;
    reinterpret_cast<float4*>(row)[tid + 256] = v1;
}

// ---------------------------------------------------------------------------
extern "C" void kernel_launch(void* const* d_in, const int* in_sizes, int n_in,
                              void* d_out, int out_size)
{
    (void)in_sizes; (void)n_in; (void)out_size;

    const float* x  = (const float*)d_in[0];
    const float* Wq = (const float*)d_in[1];
    const float* Wk = (const float*)d_in[2];
    const float* Wv = (const float*)d_in[3];
    float*       out = (float*)d_out;

    float *Q, *K, *V, *Sc;
    cudaGetSymbolAddress((void**)&Q,  g_Q);
    cudaGetSymbolAddress((void**)&K,  g_K);
    cudaGetSymbolAddress((void**)&V,  g_V);
    cudaGetSymbolAddress((void**)&Sc, g_Sc);

    const dim3 blk(NTHREADS);

    // 1) QKV projections: [NB*SEQ, DIN] x [DH, DIN]^T -> [NB*SEQ, DH]
    {
        dim3 grid(DH / BN, (NB * SEQ) / BM, 1);   // (8, 64, 1)
        gemm_nt_kernel<<<grid, blk>>>(x, Wq, Q, NB * SEQ, DH, DIN, 1.0f, 0, 0, 0);
        gemm_nt_kernel<<<grid, blk>>>(x, Wk, K, NB * SEQ, DH, DIN, 1.0f, 0, 0, 0);
        gemm_nt_kernel<<<grid, blk>>>(x, Wv, V, NB * SEQ, DH, DIN, 1.0f, 0, 0, 0);
    }

    // 2) scores = (Q @ K^T) / sqrt(SEQ), per batch
    {
        const float scale = 1.0f / sqrtf((float)SEQ);
        dim3 grid(SEQ / BN, SEQ / BM, NB);        // (16, 16, 4)
        gemm_nt_kernel<<<grid, blk>>>(Q, K, Sc, SEQ, SEQ, DH, scale,
                                      (size_t)SEQ * DH, (size_t)SEQ * DH,
                                      (size_t)SEQ * SEQ);
    }

    // 3) softmax over last dim, in place
    softmax_kernel<<<NB * SEQ, 256>>>(Sc);

    // 4) out = attn @ V, per batch
    {
        dim3 grid(DH / BN, SEQ / BM, NB);         // (8, 16, 4)
        gemm_nn_kernel<<<grid, blk>>>(Sc, V, out, SEQ, DH, SEQ,
                                      (size_t)SEQ * SEQ, (size_t)SEQ * DH,
                                      (size_t)SEQ * DH);
    }
}

// round 3
// speedup vs baseline: 3.4717x; 3.4717x over previous
#include <cuda_runtime.h>
#include <cstdint>
#include <math.h>

// Problem shape (fixed)
#define NB   4
#define SEQ  2048
#define DIN  1024
#define DH   1024

// ---------------------------------------------------------------------------
// Scratch (__device__ globals; no allocs allowed)
// ---------------------------------------------------------------------------
__device__ float g_xt[(size_t)NB * SEQ * DIN];   // tf32-rounded x       (32 MB)
__device__ float g_Wq[(size_t)DH * DIN];         // tf32-rounded weights
__device__ float g_Wk[(size_t)DH * DIN];
__device__ float g_Wv[(size_t)DH * DIN];
__device__ float g_Q [(size_t)NB * SEQ * DH];    // 32 MB
__device__ float g_K [(size_t)NB * SEQ * DH];    // 32 MB
__device__ float g_Vt[(size_t)NB * DH * SEQ];    // V transposed per batch, 32 MB
__device__ float g_Sc[(size_t)NB * SEQ * SEQ];   // scores / attn, 64 MB

// ---------------------------------------------------------------------------
__device__ __forceinline__ uint32_t smem_u32(const void* p) {
    uint32_t a;
    asm("{ .reg .u64 t; cvta.to.shared.u64 t, %1; cvt.u32.u64 %0, t; }"
        : "=r"(a) : "l"(p));
    return a;
}
__device__ __forceinline__ float rna_tf32(float x) {
    uint32_t u;
    asm("cvt.rna.tf32.f32 %0, %1;" : "=r"(u) : "f"(x));
    return __uint_as_float(u);
}

// ---------------------------------------------------------------------------
// Legacy-mma tf32 NT GEMM:  C = alpha * A @ B^T
//   A:[M,K] row-major, B:[N,K] row-major, fp32 containers holding
//   tf32-representable values. fp32 accumulate.
//   Tile 128x128x32, 8 warps (64x32 warp tile), cp.async double buffer.
// ---------------------------------------------------------------------------
constexpr int BM = 128, BN = 128, BK = 32;
constexpr int SROW    = BK + 4;            // 36 floats: conflict-free frag gather
constexpr int TILE_F  = BM * SROW;         // 4608 floats per operand tile
constexpr int STAGE_F = 2 * TILE_F;        // A+B per stage
constexpr int SMEM_BYTES = 2 * STAGE_F * 4;  // 2 stages = 73728 B

__global__ __launch_bounds__(256, 2)
void gemm_mma_nt(const float* __restrict__ A, const float* __restrict__ B,
                 float* __restrict__ C, int N, int K,
                 float alpha, int roundOut,
                 size_t sA, size_t sB, size_t sC)
{
    extern __shared__ __align__(16) float sm[];

    const int tid  = threadIdx.x;
    const int wid  = tid >> 5;
    const int lane = tid & 31;
    const int g    = lane >> 2;      // group id 0..7
    const int tig  = lane & 3;       // thread-in-group 0..3

    const int wm = wid >> 2;         // 0..1 : warp row  (64 rows)
    const int wn = wid & 3;          // 0..3 : warp col  (32 cols)

    const float* Ab = A + sA * blockIdx.z;
    const float* Bb = B + sB * blockIdx.z;
    float*       Cb = C + sC * blockIdx.z;
    const int bm = blockIdx.y * BM;
    const int bn = blockIdx.x * BN;
    const int KT = K / BK;

    const uint32_t smem_base = smem_u32(sm);

    // Per-thread cp.async assignments: 4 segs for A, 4 for B.
    // idx = i*256+tid : row = idx>>3 (0..127), seg = idx&7 (16B within 128B row)
#define LOAD_STAGE(s) do {                                                     \
        const int _buf = (s) & 1;                                              \
        const uint32_t _aB = smem_base + (uint32_t)(_buf * STAGE_F * 4);       \
        const uint32_t _bB = _aB + (uint32_t)(TILE_F * 4);                     \
        _Pragma("unroll")                                                      \
        for (int _i = 0; _i < 4; _i++) {                                       \
            const int _idx = _i * 256 + tid;                                   \
            const int _row = _idx >> 3;                                        \
            const int _seg = _idx & 7;                                         \
            const uint32_t _soff = (uint32_t)(_row * (SROW * 4) + _seg * 16);  \
            const float* _ga = Ab + (size_t)(bm + _row) * K + (s) * BK + _seg * 4; \
            const float* _gb = Bb + (size_t)(bn + _row) * K + (s) * BK + _seg * 4; \
            asm volatile("cp.async.cg.shared.global [%0], [%1], 16;"           \
                         :: "r"(_aB + _soff), "l"(_ga));                       \
            asm volatile("cp.async.cg.shared.global [%0], [%1], 16;"           \
                         :: "r"(_bB + _soff), "l"(_gb));                       \
        }                                                                      \
        asm volatile("cp.async.commit_group;" ::: "memory");                   \
    } while (0)

    float acc[4][4][4];
    #pragma unroll
    for (int i = 0; i < 4; i++)
        #pragma unroll
        for (int j = 0; j < 4; j++)
            #pragma unroll
            for (int r = 0; r < 4; r++) acc[i][j][r] = 0.0f;

    LOAD_STAGE(0);

    for (int k0 = 0; k0 < KT; k0++) {
        if (k0 + 1 < KT) {
            LOAD_STAGE(k0 + 1);
            asm volatile("cp.async.wait_group 1;" ::: "memory");
        } else {
            asm volatile("cp.async.wait_group 0;" ::: "memory");
        }
        __syncthreads();

        const float* As = sm + (k0 & 1) * STAGE_F;
        const float* Bs = As + TILE_F;
        // per-thread gather bases (conflict-free: 36*g mod 32 distinct)
        const float* pA = As + (wm * 64 + g) * SROW + tig;
        const float* pB = Bs + (wn * 32 + g) * SROW + tig;

        #pragma unroll
        for (int kk = 0; kk < BK; kk += 8) {
            uint32_t a[4][4], b[4][2];
            #pragma unroll
            for (int mf = 0; mf < 4; mf++) {
                const float* p = pA + mf * 16 * SROW + kk;
                a[mf][0] = __float_as_uint(p[0]);
                a[mf][1] = __float_as_uint(p[8 * SROW]);
                a[mf][2] = __float_as_uint(p[4]);
                a[mf][3] = __float_as_uint(p[8 * SROW + 4]);
            }
            #pragma unroll
            for (int nf = 0; nf < 4; nf++) {
                const float* p = pB + nf * 8 * SROW + kk;
                b[nf][0] = __float_as_uint(p[0]);
                b[nf][1] = __float_as_uint(p[4]);
            }
            #pragma unroll
            for (int mf = 0; mf < 4; mf++)
                #pragma unroll
                for (int nf = 0; nf < 4; nf++)
                    asm volatile(
                        "mma.sync.aligned.m16n8k8.row.col.f32.tf32.tf32.f32 "
                        "{%0,%1,%2,%3}, {%4,%5,%6,%7}, {%8,%9}, {%0,%1,%2,%3};"
                        : "+f"(acc[mf][nf][0]), "+f"(acc[mf][nf][1]),
                          "+f"(acc[mf][nf][2]), "+f"(acc[mf][nf][3])
                        : "r"(a[mf][0]), "r"(a[mf][1]), "r"(a[mf][2]), "r"(a[mf][3]),
                          "r"(b[nf][0]), "r"(b[nf][1]));
        }
        __syncthreads();
    }
#undef LOAD_STAGE

    // Epilogue: direct float2 stores.
    // c0: (row g,   col 2*tig)  c1: (g, 2*tig+1)  c2: (g+8, 2*tig)  c3: (g+8, 2*tig+1)
    const int mBase = bm + wm * 64 + g;
    const int nBase = bn + wn * 32 + 2 * tig;
    #pragma unroll
    for (int mf = 0; mf < 4; mf++) {
        #pragma unroll
        for (int nf = 0; nf < 4; nf++) {
            float v0 = acc[mf][nf][0] * alpha, v1 = acc[mf][nf][1] * alpha;
            float v2 = acc[mf][nf][2] * alpha, v3 = acc[mf][nf][3] * alpha;
            if (roundOut) {
                v0 = rna_tf32(v0); v1 = rna_tf32(v1);
                v2 = rna_tf32(v2); v3 = rna_tf32(v3);
            }
            const size_t r0 = (size_t)(mBase + mf * 16) * N + nBase + nf * 8;
            const size_t r1 = r0 + 8 * (size_t)N;
            *reinterpret_cast<float2*>(&Cb[r0]) = make_float2(v0, v1);
            *reinterpret_cast<float2*>(&Cb[r1]) = make_float2(v2, v3);
        }
    }
}

// ---------------------------------------------------------------------------
// fp32 -> tf32 (round-to-nearest) element convert
// ---------------------------------------------------------------------------
__global__ __launch_bounds__(256)
void cvt_tf32_kernel(const float* __restrict__ in, float* __restrict__ out, int n4)
{
    int i = blockIdx.x * 256 + threadIdx.x;
    if (i < n4) {
        float4 v = reinterpret_cast<const float4*>(in)[i];
        v.x = rna_tf32(v.x); v.y = rna_tf32(v.y);
        v.z = rna_tf32(v.z); v.w = rna_tf32(v.w);
        reinterpret_cast<float4*>(out)[i] = v;
    }
}

// ---------------------------------------------------------------------------
// In-place row softmax, output rounded to tf32 (feeds PV MMA).
// ---------------------------------------------------------------------------
__global__ __launch_bounds__(256)
void softmax_kernel(float* __restrict__ S)
{
    float* row = S + (size_t)blockIdx.x * SEQ;
    const int tid  = threadIdx.x;
    const int lane = tid & 31;
    const int warp = tid >> 5;

    float4 v0 = reinterpret_cast<float4*>(row)[tid];
    float4 v1 = reinterpret_cast<float4*>(row)[tid + 256];

    __shared__ float red[8];

    float m = fmaxf(fmaxf(fmaxf(v0.x, v0.y), fmaxf(v0.z, v0.w)),
                    fmaxf(fmaxf(v1.x, v1.y), fmaxf(v1.z, v1.w)));
    #pragma unroll
    for (int o = 16; o > 0; o >>= 1) m = fmaxf(m, __shfl_xor_sync(0xFFFFFFFFu, m, o));
    if (lane == 0) red[warp] = m;
    __syncthreads();
    m = red[0];
    #pragma unroll
    for (int w = 1; w < 8; w++) m = fmaxf(m, red[w]);
    __syncthreads();

    v0.x = __expf(v0.x - m); v0.y = __expf(v0.y - m);
    v0.z = __expf(v0.z - m); v0.w = __expf(v0.w - m);
    v1.x = __expf(v1.x - m); v1.y = __expf(v1.y - m);
    v1.z = __expf(v1.z - m); v1.w = __expf(v1.w - m);

    float s = (v0.x + v0.y + v0.z + v0.w) + (v1.x + v1.y + v1.z + v1.w);
    #pragma unroll
    for (int o = 16; o > 0; o >>= 1) s += __shfl_xor_sync(0xFFFFFFFFu, s, o);
    if (lane == 0) red[warp] = s;
    __syncthreads();
    s = red[0];
    #pragma unroll
    for (int w = 1; w < 8; w++) s += red[w];

    float inv = 1.0f / s;
    v0.x = rna_tf32(v0.x * inv); v0.y = rna_tf32(v0.y * inv);
    v0.z = rna_tf32(v0.z * inv); v0.w = rna_tf32(v0.w * inv);
    v1.x = rna_tf32(v1.x * inv); v1.y = rna_tf32(v1.y * inv);
    v1.z = rna_tf32(v1.z * inv); v1.w = rna_tf32(v1.w * inv);

    reinterpret_cast<float4*>(row)[tid]       = v0;
    reinterpret_cast<float4*>(row)[tid + 256] = v1;
}

// ---------------------------------------------------------------------------
extern "C" void kernel_launch(void* const* d_in, const int* in_sizes, int n_in,
                              void* d_out, int out_size)
{
    (void)in_sizes; (void)n_in; (void)out_size;

    const float* x  = (const float*)d_in[0];
    const float* Wq = (const float*)d_in[1];
    const float* Wk = (const float*)d_in[2];
    const float* Wv = (const float*)d_in[3];
    float*       out = (float*)d_out;

    float *xt, *wq, *wk, *wv, *Q, *K, *Vt, *Sc;
    cudaGetSymbolAddress((void**)&xt, g_xt);
    cudaGetSymbolAddress((void**)&wq, g_Wq);
    cudaGetSymbolAddress((void**)&wk, g_Wk);
    cudaGetSymbolAddress((void**)&wv, g_Wv);
    cudaGetSymbolAddress((void**)&Q,  g_Q);
    cudaGetSymbolAddress((void**)&K,  g_K);
    cudaGetSymbolAddress((void**)&Vt, g_Vt);
    cudaGetSymbolAddress((void**)&Sc, g_Sc);

    cudaFuncSetAttribute(gemm_mma_nt, cudaFuncAttributeMaxDynamicSharedMemorySize,
                         SMEM_BYTES);

    // 0) round inputs to tf32 (rna)
    {
        int n4x = (NB * SEQ * DIN) / 4;
        int n4w = (DH * DIN) / 4;
        cvt_tf32_kernel<<<n4x / 256, 256>>>(x,  xt, n4x);
        cvt_tf32_kernel<<<n4w / 256, 256>>>(Wq, wq, n4w);
        cvt_tf32_kernel<<<n4w / 256, 256>>>(Wk, wk, n4w);
        cvt_tf32_kernel<<<n4w / 256, 256>>>(Wv, wv, n4w);
    }

    // 1) Q = xt @ Wq^T, K = xt @ Wk^T
    {
        dim3 grid(DH / BN, (NB * SEQ) / BM, 1);
        gemm_mma_nt<<<grid, 256, SMEM_BYTES>>>(xt, wq, Q, DH, DIN, 1.0f, 1, 0, 0, 0);
        gemm_mma_nt<<<grid, 256, SMEM_BYTES>>>(xt, wk, K, DH, DIN, 1.0f, 1, 0, 0, 0);
    }

    // 2) V^T_b = Wv @ x_b^T : NT GEMM, M=DH, N=SEQ, K=DIN (per batch)
    {
        dim3 grid(SEQ / BN, DH / BM, NB);
        gemm_mma_nt<<<grid, 256, SMEM_BYTES>>>(wv, xt, Vt, SEQ, DIN, 1.0f, 1,
                                               0, (size_t)SEQ * DIN,
                                               (size_t)DH * SEQ);
    }

    // 3) scores = (Q_b @ K_b^T) / sqrt(SEQ)
    {
        const float scale = 1.0f / sqrtf((float)SEQ);
        dim3 grid(SEQ / BN, SEQ / BM, NB);
        gemm_mma_nt<<<grid, 256, SMEM_BYTES>>>(Q, K, Sc, SEQ, DH, scale, 0,
                                               (size_t)SEQ * DH, (size_t)SEQ * DH,
                                               (size_t)SEQ * SEQ);
    }

    // 4) softmax (in place, tf32-rounded output)
    softmax_kernel<<<NB * SEQ, 256>>>(Sc);

    // 5) out_b = attn_b @ (V^T_b)^T : NT GEMM, M=SEQ, N=DH, K=SEQ
    {
        dim3 grid(DH / BN, SEQ / BM, NB);
        gemm_mma_nt<<<grid, 256, SMEM_BYTES>>>(Sc, Vt, out, DH, SEQ, 1.0f, 0,
                                               (size_t)SEQ * SEQ, (size_t)DH * SEQ,
                                               (size_t)SEQ * DH);
    }
}

// round 4
// speedup vs baseline: 4.1325x; 1.1903x over previous
#include <cuda_runtime.h>
#include <cstdint>
#include <math.h>

// Problem shape (fixed)
#define NB   4
#define SEQ  2048
#define DIN  1024
#define DH   1024

// ---------------------------------------------------------------------------
// Scratch (__device__ globals; no allocs allowed)
// ---------------------------------------------------------------------------
__device__ float g_xt [(size_t)NB * SEQ * DIN];      // tf32-rounded x   (32 MB)
__device__ float g_Wqk[(size_t)2 * DH * DIN];        // [Wq; Wk] rounded (8 MB)
__device__ float g_Wv [(size_t)DH * DIN];            // rounded          (4 MB)
__device__ float g_QK [(size_t)NB * SEQ * 2 * DH];   // [Q | K] cols     (64 MB)
__device__ float g_Vt [(size_t)NB * DH * SEQ];       // V^T per batch    (32 MB)
__device__ float g_Sc [(size_t)NB * SEQ * SEQ];      // scores/attn      (64 MB)

// ---------------------------------------------------------------------------
__device__ __forceinline__ uint32_t smem_u32(const void* p) {
    uint32_t a;
    asm("{ .reg .u64 t; cvta.to.shared.u64 t, %1; cvt.u32.u64 %0, t; }"
        : "=r"(a) : "l"(p));
    return a;
}
__device__ __forceinline__ float rna_tf32(float x) {
    uint32_t u;
    asm("cvt.rna.tf32.f32 %0, %1;" : "=r"(u) : "f"(x));
    return __uint_as_float(u);
}

// ---------------------------------------------------------------------------
// Legacy-mma tf32 NT GEMM:  C = alpha * A @ B^T
//   A:[M,K] ldA, B:[N,K] ldB, row-major fp32 containers holding tf32 values.
//   Tile 128x128x32, 8 warps (64x32 warp tile), 3-stage cp.async, XOR swizzle.
//   M = gridDim.y*128, N = gridDim.x*128 implied.
// ---------------------------------------------------------------------------
constexpr int BM = 128, BN = 128, BK = 32, NST = 3;
constexpr int TILE_F  = BM * BK;           // 4096 floats / 16 KB per operand
constexpr int STAGE_F = 2 * TILE_F;        // 32 KB per stage
constexpr int SMEM_BYTES = NST * STAGE_F * 4;   // 98304 B

__global__ __launch_bounds__(256, 2)
void gemm_mma_nt(const float* __restrict__ A, const float* __restrict__ B,
                 float* __restrict__ C, int K,
                 int ldA, int ldB, int ldC,
                 float alpha, int roundOut,
                 size_t sA, size_t sB, size_t sC)
{
    extern __shared__ __align__(16) float sm[];

    const int tid  = threadIdx.x;
    const int wid  = tid >> 5;
    const int lane = tid & 31;
    const int g    = lane >> 2;      // 0..7
    const int tig  = lane & 3;       // 0..3

    const int wm = wid >> 2;         // 0..1 : 64-row warp slab
    const int wn = wid & 3;          // 0..3 : 32-col warp slab

    const float* Ab = A + sA * blockIdx.z;
    const float* Bb = B + sB * blockIdx.z;
    float*       Cb = C + sC * blockIdx.z;
    const int bm = blockIdx.y * BM;
    const int bn = blockIdx.x * BN;
    const int KT = K / BK;

    const uint32_t smem_base = smem_u32(sm);

    // cp.async stage loader. 128 rows x 32 floats (128 B) per operand.
    // 16B chunk c of row r goes to physical chunk c ^ (r & 7).
#define LOAD_STAGE(s) do {                                                     \
        const uint32_t _base = smem_base + (uint32_t)(((s) % NST) * STAGE_F * 4); \
        const uint32_t _bB   = _base + (uint32_t)(TILE_F * 4);                 \
        _Pragma("unroll")                                                      \
        for (int _i = 0; _i < 4; _i++) {                                       \
            const int _idx = _i * 256 + tid;                                   \
            const int _row = _idx >> 3;                                        \
            const int _seg = _idx & 7;                                         \
            const uint32_t _soff = (uint32_t)(_row * 128 +                     \
                                   ((_seg ^ (_row & 7)) << 4));                \
            const float* _ga = Ab + (size_t)(bm + _row) * ldA + (s) * BK + _seg * 4; \
            const float* _gb = Bb + (size_t)(bn + _row) * ldB + (s) * BK + _seg * 4; \
            asm volatile("cp.async.cg.shared.global [%0], [%1], 16;"           \
                         :: "r"(_base + _soff), "l"(_ga));                     \
            asm volatile("cp.async.cg.shared.global [%0], [%1], 16;"           \
                         :: "r"(_bB + _soff), "l"(_gb));                       \
        }                                                                      \
        asm volatile("cp.async.commit_group;" ::: "memory");                   \
    } while (0)

    float acc[4][4][4];
    #pragma unroll
    for (int i = 0; i < 4; i++)
        #pragma unroll
        for (int j = 0; j < 4; j++)
            #pragma unroll
            for (int r = 0; r < 4; r++) acc[i][j][r] = 0.0f;

    LOAD_STAGE(0);
    LOAD_STAGE(1);

    for (int k0 = 0; k0 < KT; k0++) {
        if (k0 + 1 < KT) asm volatile("cp.async.wait_group 1;" ::: "memory");
        else             asm volatile("cp.async.wait_group 0;" ::: "memory");
        __syncthreads();   // stage k0 ready for everyone; everyone done with k0-1

        if (k0 + 2 < KT) LOAD_STAGE(k0 + 2);   // overwrites buf (k0-1)%3 — safe

        const float* As = sm + (k0 % NST) * STAGE_F;
        const float* Bs = As + TILE_F;

        #pragma unroll
        for (int ks = 0; ks < BK / 8; ks++) {
            const int c0 = 2 * ks;          // 16B-chunk of col kk+tig
            const int c1 = 2 * ks + 1;      // chunk of col kk+tig+4
            uint32_t a[4][4], b[4][2];
            #pragma unroll
            for (int mf = 0; mf < 4; mf++) {
                const int r0 = wm * 64 + mf * 16 + g;     // (r0 & 7) == g
                const int r1 = r0 + 8;
                a[mf][0] = __float_as_uint(As[(r0 << 5) + ((c0 ^ g) << 2) + tig]);
                a[mf][1] = __float_as_uint(As[(r1 << 5) + ((c0 ^ g) << 2) + tig]);
                a[mf][2] = __float_as_uint(As[(r0 << 5) + ((c1 ^ g) << 2) + tig]);
                a[mf][3] = __float_as_uint(As[(r1 << 5) + ((c1 ^ g) << 2) + tig]);
            }
            #pragma unroll
            for (int nf = 0; nf < 4; nf++) {
                const int rb = wn * 32 + nf * 8 + g;      // (rb & 7) == g
                b[nf][0] = __float_as_uint(Bs[(rb << 5) + ((c0 ^ g) << 2) + tig]);
                b[nf][1] = __float_as_uint(Bs[(rb << 5) + ((c1 ^ g) << 2) + tig]);
            }
            #pragma unroll
            for (int mf = 0; mf < 4; mf++)
                #pragma unroll
                for (int nf = 0; nf < 4; nf++)
                    asm volatile(
                        "mma.sync.aligned.m16n8k8.row.col.f32.tf32.tf32.f32 "
                        "{%0,%1,%2,%3}, {%4,%5,%6,%7}, {%8,%9}, {%0,%1,%2,%3};"
                        : "+f"(acc[mf][nf][0]), "+f"(acc[mf][nf][1]),
                          "+f"(acc[mf][nf][2]), "+f"(acc[mf][nf][3])
                        : "r"(a[mf][0]), "r"(a[mf][1]), "r"(a[mf][2]), "r"(a[mf][3]),
                          "r"(b[nf][0]), "r"(b[nf][1]));
        }
    }
#undef LOAD_STAGE

    // Epilogue: direct float2 stores.
    const int mBase = bm + wm * 64 + g;
    const int nBase = bn + wn * 32 + 2 * tig;
    #pragma unroll
    for (int mf = 0; mf < 4; mf++) {
        #pragma unroll
        for (int nf = 0; nf < 4; nf++) {
            float v0 = acc[mf][nf][0] * alpha, v1 = acc[mf][nf][1] * alpha;
            float v2 = acc[mf][nf][2] * alpha, v3 = acc[mf][nf][3] * alpha;
            if (roundOut) {
                v0 = rna_tf32(v0); v1 = rna_tf32(v1);
                v2 = rna_tf32(v2); v3 = rna_tf32(v3);
            }
            const size_t r0 = (size_t)(mBase + mf * 16) * ldC + nBase + nf * 8;
            const size_t r1 = r0 + 8 * (size_t)ldC;
            *reinterpret_cast<float2*>(&Cb[r0]) = make_float2(v0, v1);
            *reinterpret_cast<float2*>(&Cb[r1]) = make_float2(v2, v3);
        }
    }
}

// ---------------------------------------------------------------------------
// fp32 -> tf32 (rna) convert, 4 float4 per thread for MLP.
// n4 must be a multiple of 1024 (true for all our sizes).
// ---------------------------------------------------------------------------
__global__ __launch_bounds__(256)
void cvt_tf32_kernel(const float4* __restrict__ in, float4* __restrict__ out)
{
    const int base = blockIdx.x * 1024 + threadIdx.x;
    float4 v[4];
    #pragma unroll
    for (int j = 0; j < 4; j++) v[j] = in[base + j * 256];
    #pragma unroll
    for (int j = 0; j < 4; j++) {
        v[j].x = rna_tf32(v[j].x); v[j].y = rna_tf32(v[j].y);
        v[j].z = rna_tf32(v[j].z); v[j].w = rna_tf32(v[j].w);
    }
    #pragma unroll
    for (int j = 0; j < 4; j++) out[base + j * 256] = v[j];
}

// ---------------------------------------------------------------------------
// In-place row softmax, output rounded to tf32 (feeds PV MMA).
// ---------------------------------------------------------------------------
__global__ __launch_bounds__(256)
void softmax_kernel(float* __restrict__ S)
{
    float* row = S + (size_t)blockIdx.x * SEQ;
    const int tid  = threadIdx.x;
    const int lane = tid & 31;
    const int warp = tid >> 5;

    float4 v0 = reinterpret_cast<float4*>(row)[tid];
    float4 v1 = reinterpret_cast<float4*>(row)[tid + 256];

    __shared__ float red[8];

    float m = fmaxf(fmaxf(fmaxf(v0.x, v0.y), fmaxf(v0.z, v0.w)),
                    fmaxf(fmaxf(v1.x, v1.y), fmaxf(v1.z, v1.w)));
    #pragma unroll
    for (int o = 16; o > 0; o >>= 1) m = fmaxf(m, __shfl_xor_sync(0xFFFFFFFFu, m, o));
    if (lane == 0) red[warp] = m;
    __syncthreads();
    m = red[0];
    #pragma unroll
    for (int w = 1; w < 8; w++) m = fmaxf(m, red[w]);
    __syncthreads();

    v0.x = __expf(v0.x - m); v0.y = __expf(v0.y - m);
    v0.z = __expf(v0.z - m); v0.w = __expf(v0.w - m);
    v1.x = __expf(v1.x - m); v1.y = __expf(v1.y - m);
    v1.z = __expf(v1.z - m); v1.w = __expf(v1.w - m);

    float s = (v0.x + v0.y + v0.z + v0.w) + (v1.x + v1.y + v1.z + v1.w);
    #pragma unroll
    for (int o = 16; o > 0; o >>= 1) s += __shfl_xor_sync(0xFFFFFFFFu, s, o);
    if (lane == 0) red[warp] = s;
    __syncthreads();
    s = red[0];
    #pragma unroll
    for (int w = 1; w < 8; w++) s += red[w];

    float inv = 1.0f / s;
    v0.x = rna_tf32(v0.x * inv); v0.y = rna_tf32(v0.y * inv);
    v0.z = rna_tf32(v0.z * inv); v0.w = rna_tf32(v0.w * inv);
    v1.x = rna_tf32(v1.x * inv); v1.y = rna_tf32(v1.y * inv);
    v1.z = rna_tf32(v1.z * inv); v1.w = rna_tf32(v1.w * inv);

    reinterpret_cast<float4*>(row)[tid]       = v0;
    reinterpret_cast<float4*>(row)[tid + 256] = v1;
}

// ---------------------------------------------------------------------------
extern "C" void kernel_launch(void* const* d_in, const int* in_sizes, int n_in,
                              void* d_out, int out_size)
{
    (void)in_sizes; (void)n_in; (void)out_size;

    const float* x  = (const float*)d_in[0];
    const float* Wq = (const float*)d_in[1];
    const float* Wk = (const float*)d_in[2];
    const float* Wv = (const float*)d_in[3];
    float*       out = (float*)d_out;

    float *xt, *wqk, *wv, *QK, *Vt, *Sc;
    cudaGetSymbolAddress((void**)&xt,  g_xt);
    cudaGetSymbolAddress((void**)&wqk, g_Wqk);
    cudaGetSymbolAddress((void**)&wv,  g_Wv);
    cudaGetSymbolAddress((void**)&QK,  g_QK);
    cudaGetSymbolAddress((void**)&Vt,  g_Vt);
    cudaGetSymbolAddress((void**)&Sc,  g_Sc);

    cudaFuncSetAttribute(gemm_mma_nt, cudaFuncAttributeMaxDynamicSharedMemorySize,
                         SMEM_BYTES);

    // 0) round inputs to tf32 (rna). Each block: 1024 float4.
    {
        const int n4x = (NB * SEQ * DIN) / 4;   // 2097152 -> 2048 blocks
        const int n4w = (DH * DIN) / 4;         // 262144  -> 256 blocks
        cvt_tf32_kernel<<<n4x / 1024, 256>>>((const float4*)x,  (float4*)xt);
        cvt_tf32_kernel<<<n4w / 1024, 256>>>((const float4*)Wq, (float4*)wqk);
        cvt_tf32_kernel<<<n4w / 1024, 256>>>((const float4*)Wk,
                                             (float4*)(wqk + (size_t)DH * DIN));
        cvt_tf32_kernel<<<n4w / 1024, 256>>>((const float4*)Wv, (float4*)wv);
    }

    // 1) [Q|K] = xt @ [Wq;Wk]^T : one GEMM, N = 2*DH
    {
        dim3 grid((2 * DH) / BN, (NB * SEQ) / BM, 1);     // (16, 64)
        gemm_mma_nt<<<grid, 256, SMEM_BYTES>>>(xt, wqk, QK, DIN,
                                               DIN, DIN, 2 * DH,
                                               1.0f, 1, 0, 0, 0);
    }

    // 2) V^T_b = Wv @ x_b^T : M=DH, N=SEQ, K=DIN (per batch)
    {
        dim3 grid(SEQ / BN, DH / BM, NB);                 // (16, 8, 4)
        gemm_mma_nt<<<grid, 256, SMEM_BYTES>>>(wv, xt, Vt, DIN,
                                               DIN, DIN, SEQ,
                                               1.0f, 1,
                                               0, (size_t)SEQ * DIN,
                                               (size_t)DH * SEQ);
    }

    // 3) scores_b = (Q_b @ K_b^T) / sqrt(SEQ)
    //    Q_b = QK rows [b*SEQ..), cols [0,DH);  K_b = same rows, cols [DH,2DH)
    {
        const float scale = 1.0f / sqrtf((float)SEQ);
        dim3 grid(SEQ / BN, SEQ / BM, NB);                // (16, 16, 4)
        gemm_mma_nt<<<grid, 256, SMEM_BYTES>>>(QK, QK + DH, Sc, DH,
                                               2 * DH, 2 * DH, SEQ,
                                               scale, 0,
                                               (size_t)SEQ * 2 * DH,
                                               (size_t)SEQ * 2 * DH,
                                               (size_t)SEQ * SEQ);
    }

    // 4) softmax (in place, tf32-rounded output)
    softmax_kernel<<<NB * SEQ, 256>>>(Sc);

    // 5) out_b = attn_b @ (V^T_b)^T : M=SEQ, N=DH, K=SEQ
    {
        dim3 grid(DH / BN, SEQ / BM, NB);                 // (8, 16, 4)
        gemm_mma_nt<<<grid, 256, SMEM_BYTES>>>(Sc, Vt, out, SEQ,
                                               SEQ, SEQ, DH,
                                               1.0f, 0,
                                               (size_t)SEQ * SEQ,
                                               (size_t)DH * SEQ,
                                               (size_t)SEQ * DH);
    }
}

// round 6
// speedup vs baseline: 7.4804x; 1.8101x over previous
#include <cuda_runtime.h>
#include <cuda_fp16.h>
#include <cstdint>
#include <math.h>

// Problem shape (fixed)
#define NB   4
#define SEQ  2048
#define DIN  1024
#define DH   1024

// ---------------------------------------------------------------------------
// Scratch (__device__ globals; no allocs allowed)
// ---------------------------------------------------------------------------
__device__ __half g_xh [(size_t)NB * SEQ * DIN];      // fp16 x            (16 MB)
__device__ __half g_Wqk[(size_t)2 * DH * DIN];        // [Wq; Wk] fp16     (4 MB)
__device__ __half g_Wv [(size_t)DH * DIN];            // fp16              (2 MB)
__device__ __half g_QK [(size_t)NB * SEQ * 2 * DH];   // [Q | K] fp16      (32 MB)
__device__ __half g_Vt [(size_t)NB * DH * SEQ];       // V^T fp16          (16 MB)
__device__ float  g_Sc [(size_t)NB * SEQ * SEQ];      // scores fp32       (64 MB)
__device__ __half g_At [(size_t)NB * SEQ * SEQ];      // attn fp16         (32 MB)

// ---------------------------------------------------------------------------
__device__ __forceinline__ uint32_t smem_u32(const void* p) {
    uint32_t a;
    asm("{ .reg .u64 t; cvta.to.shared.u64 t, %1; cvt.u32.u64 %0, t; }"
        : "=r"(a) : "l"(p));
    return a;
}

// ---------------------------------------------------------------------------
// fp16 m16n8k16 NT GEMM:  C = alpha * A @ B^T
//   A:[M,K] ldA halfs, B:[N,K] ldB halfs (both K-contiguous), fp32 accum.
//   Tile 128x128x64, 8 warps (64x32 warp tile), 3-stage cp.async, XOR swizzle.
//   OUT_HALF: C is __half (ldC halfs) else float (ldC floats).
// ---------------------------------------------------------------------------
constexpr int BM = 128, BN = 128, BK = 64, NST = 3;
constexpr int TILE_H  = BM * BK;                 // 8192 halfs = 16 KB per operand
constexpr int STAGE_H = 2 * TILE_H;              // 32 KB per stage
constexpr int SMEM_BYTES = NST * STAGE_H * 2;    // 98304 B

template <bool OUT_HALF>
__global__ __launch_bounds__(256, 2)
void gemm_h16_nt(const __half* __restrict__ A, const __half* __restrict__ B,
                 void* __restrict__ Cv, int K,
                 int ldA, int ldB, int ldC, float alpha,
                 size_t sA, size_t sB, size_t sC)
{
    extern __shared__ __align__(16) __half sm[];

    const int tid  = threadIdx.x;
    const int wid  = tid >> 5;
    const int lane = tid & 31;
    const int g    = lane >> 2;      // 0..7
    const int tig  = lane & 3;       // 0..3

    const int wm = wid >> 2;         // 0..1 : 64-row warp slab
    const int wn = wid & 3;          // 0..3 : 32-col warp slab

    const __half* Ab = A + sA * blockIdx.z;
    const __half* Bb = B + sB * blockIdx.z;
    const int bm = blockIdx.y * BM;
    const int bn = blockIdx.x * BN;
    const int KT = K / BK;

    const uint32_t smem_base = smem_u32(sm);

    // Stage loader: per operand 128 rows x 64 halfs (128 B) = 8 x 16B chunks.
    // Chunk c of row r stored at physical chunk c ^ (r & 7).
#define LOAD_STAGE(s) do {                                                     \
        const uint32_t _base = smem_base + (uint32_t)(((s) % NST) * STAGE_H * 2); \
        const uint32_t _bB   = _base + (uint32_t)(TILE_H * 2);                 \
        _Pragma("unroll")                                                      \
        for (int _i = 0; _i < 4; _i++) {                                       \
            const int _idx = _i * 256 + tid;                                   \
            const int _row = _idx >> 3;                                        \
            const int _seg = _idx & 7;                                         \
            const uint32_t _soff = (uint32_t)(_row * 128 +                     \
                                   ((_seg ^ (_row & 7)) << 4));                \
            const __half* _ga = Ab + (size_t)(bm + _row) * ldA + (s) * BK + _seg * 8; \
            const __half* _gb = Bb + (size_t)(bn + _row) * ldB + (s) * BK + _seg * 8; \
            asm volatile("cp.async.cg.shared.global [%0], [%1], 16;"           \
                         :: "r"(_base + _soff), "l"(_ga));                     \
            asm volatile("cp.async.cg.shared.global [%0], [%1], 16;"           \
                         :: "r"(_bB + _soff), "l"(_gb));                       \
        }                                                                      \
        asm volatile("cp.async.commit_group;" ::: "memory");                   \
    } while (0)

    float acc[4][4][4];
    #pragma unroll
    for (int i = 0; i < 4; i++)
        #pragma unroll
        for (int j = 0; j < 4; j++)
            #pragma unroll
            for (int r = 0; r < 4; r++) acc[i][j][r] = 0.0f;

    LOAD_STAGE(0);
    LOAD_STAGE(1);

    for (int k0 = 0; k0 < KT; k0++) {
        if (k0 + 1 < KT) asm volatile("cp.async.wait_group 1;" ::: "memory");
        else             asm volatile("cp.async.wait_group 0;" ::: "memory");
        __syncthreads();

        if (k0 + 2 < KT) LOAD_STAGE(k0 + 2);

        // View stage as 32-bit words: row stride 32 words, chunk = 4 words.
        const uint32_t* As = reinterpret_cast<const uint32_t*>(
                                 sm + (k0 % NST) * STAGE_H);
        const uint32_t* Bs = As + TILE_H / 2;

        #pragma unroll
        for (int ks = 0; ks < BK / 16; ks++) {
            const int c0 = 2 * ks;         // chunk holding k = 16ks + 2tig(+1)
            const int c1 = 2 * ks + 1;     // chunk holding k = 16ks + 8 + 2tig(+1)
            uint32_t a[4][4], b[4][2];
            #pragma unroll
            for (int mf = 0; mf < 4; mf++) {
                const int r0 = wm * 64 + mf * 16 + g;   // (r0 & 7) == g
                const int r1 = r0 + 8;
                a[mf][0] = As[(r0 << 5) + ((c0 ^ g) << 2) + tig];
                a[mf][1] = As[(r1 << 5) + ((c0 ^ g) << 2) + tig];
                a[mf][2] = As[(r0 << 5) + ((c1 ^ g) << 2) + tig];
                a[mf][3] = As[(r1 << 5) + ((c1 ^ g) << 2) + tig];
            }
            #pragma unroll
            for (int nf = 0; nf < 4; nf++) {
                const int rb = wn * 32 + nf * 8 + g;    // (rb & 7) == g
                b[nf][0] = Bs[(rb << 5) + ((c0 ^ g) << 2) + tig];
                b[nf][1] = Bs[(rb << 5) + ((c1 ^ g) << 2) + tig];
            }
            #pragma unroll
            for (int mf = 0; mf < 4; mf++)
                #pragma unroll
                for (int nf = 0; nf < 4; nf++)
                    asm volatile(
                        "mma.sync.aligned.m16n8k16.row.col.f32.f16.f16.f32 "
                        "{%0,%1,%2,%3}, {%4,%5,%6,%7}, {%8,%9}, {%0,%1,%2,%3};"
                        : "+f"(acc[mf][nf][0]), "+f"(acc[mf][nf][1]),
                          "+f"(acc[mf][nf][2]), "+f"(acc[mf][nf][3])
                        : "r"(a[mf][0]), "r"(a[mf][1]), "r"(a[mf][2]), "r"(a[mf][3]),
                          "r"(b[nf][0]), "r"(b[nf][1]));
        }
    }
#undef LOAD_STAGE

    // Epilogue
    const int mBase = bm + wm * 64 + g;
    const int nBase = bn + wn * 32 + 2 * tig;
    #pragma unroll
    for (int mf = 0; mf < 4; mf++) {
        #pragma unroll
        for (int nf = 0; nf < 4; nf++) {
            const float v0 = acc[mf][nf][0] * alpha, v1 = acc[mf][nf][1] * alpha;
            const float v2 = acc[mf][nf][2] * alpha, v3 = acc[mf][nf][3] * alpha;
            const size_t r0 = (size_t)(mBase + mf * 16) * ldC + nBase + nf * 8;
            const size_t r1 = r0 + 8 * (size_t)ldC;
            if (OUT_HALF) {
                __half* Ch = (__half*)Cv + sC * blockIdx.z;
                *reinterpret_cast<__half2*>(&Ch[r0]) =
                    __float22half2_rn(make_float2(v0, v1));
                *reinterpret_cast<__half2*>(&Ch[r1]) =
                    __float22half2_rn(make_float2(v2, v3));
            } else {
                float* Cf = (float*)Cv + sC * blockIdx.z;
                *reinterpret_cast<float2*>(&Cf[r0]) = make_float2(v0, v1);
                *reinterpret_cast<float2*>(&Cf[r1]) = make_float2(v2, v3);
            }
        }
    }
}

// ---------------------------------------------------------------------------
// fp32 -> fp16 convert: each thread handles 8 floats (2x float4 -> 1x uint4).
// n must be a multiple of 2048.
// ---------------------------------------------------------------------------
__global__ __launch_bounds__(256)
void cvt_h_kernel(const float4* __restrict__ in, uint4* __restrict__ out)
{
    const int i = blockIdx.x * 256 + threadIdx.x;
    const float4 u = in[2 * i], v = in[2 * i + 1];
    __half2 h0 = __float22half2_rn(make_float2(u.x, u.y));
    __half2 h1 = __float22half2_rn(make_float2(u.z, u.w));
    __half2 h2 = __float22half2_rn(make_float2(v.x, v.y));
    __half2 h3 = __float22half2_rn(make_float2(v.z, v.w));
    uint4 o;
    o.x = *reinterpret_cast<uint32_t*>(&h0);
    o.y = *reinterpret_cast<uint32_t*>(&h1);
    o.z = *reinterpret_cast<uint32_t*>(&h2);
    o.w = *reinterpret_cast<uint32_t*>(&h3);
    out[i] = o;
}

// ---------------------------------------------------------------------------
// Row softmax: read fp32 scores, write fp16 attn.
// One block per row (2048): 256 threads x 8 contiguous floats.
// ---------------------------------------------------------------------------
__global__ __launch_bounds__(256)
void softmax_kernel(const float* __restrict__ S, __half* __restrict__ P)
{
    const float* row = S + (size_t)blockIdx.x * SEQ;
    __half*      orow = P + (size_t)blockIdx.x * SEQ;
    const int tid  = threadIdx.x;
    const int lane = tid & 31;
    const int warp = tid >> 5;

    float4 v0 = reinterpret_cast<const float4*>(row)[2 * tid];
    float4 v1 = reinterpret_cast<const float4*>(row)[2 * tid + 1];

    __shared__ float red[8];

    float m = fmaxf(fmaxf(fmaxf(v0.x, v0.y), fmaxf(v0.z, v0.w)),
                    fmaxf(fmaxf(v1.x, v1.y), fmaxf(v1.z, v1.w)));
    #pragma unroll
    for (int o = 16; o > 0; o >>= 1) m = fmaxf(m, __shfl_xor_sync(0xFFFFFFFFu, m, o));
    if (lane == 0) red[warp] = m;
    __syncthreads();
    m = red[0];
    #pragma unroll
    for (int w = 1; w < 8; w++) m = fmaxf(m, red[w]);
    __syncthreads();

    v0.x = __expf(v0.x - m); v0.y = __expf(v0.y - m);
    v0.z = __expf(v0.z - m); v0.w = __expf(v0.w - m);
    v1.x = __expf(v1.x - m); v1.y = __expf(v1.y - m);
    v1.z = __expf(v1.z - m); v1.w = __expf(v1.w - m);

    float s = (v0.x + v0.y + v0.z + v0.w) + (v1.x + v1.y + v1.z + v1.w);
    #pragma unroll
    for (int o = 16; o > 0; o >>= 1) s += __shfl_xor_sync(0xFFFFFFFFu, s, o);
    if (lane == 0) red[warp] = s;
    __syncthreads();
    s = red[0];
    #pragma unroll
    for (int w = 1; w < 8; w++) s += red[w];

    const float inv = 1.0f / s;
    __half2 h0 = __float22half2_rn(make_float2(v0.x * inv, v0.y * inv));
    __half2 h1 = __float22half2_rn(make_float2(v0.z * inv, v0.w * inv));
    __half2 h2 = __float22half2_rn(make_float2(v1.x * inv, v1.y * inv));
    __half2 h3 = __float22half2_rn(make_float2(v1.z * inv, v1.w * inv));
    uint4 o;
    o.x = *reinterpret_cast<uint32_t*>(&h0);
    o.y = *reinterpret_cast<uint32_t*>(&h1);
    o.z = *reinterpret_cast<uint32_t*>(&h2);
    o.w = *reinterpret_cast<uint32_t*>(&h3);
    reinterpret_cast<uint4*>(orow)[tid] = o;
}

// ---------------------------------------------------------------------------
extern "C" void kernel_launch(void* const* d_in, const int* in_sizes, int n_in,
                              void* d_out, int out_size)
{
    (void)in_sizes; (void)n_in; (void)out_size;

    const float* x  = (const float*)d_in[0];
    const float* Wq = (const float*)d_in[1];
    const float* Wk = (const float*)d_in[2];
    const float* Wv = (const float*)d_in[3];
    float*       out = (float*)d_out;

    __half *xh, *wqk, *wv, *QK, *Vt, *At;
    float *Sc;
    cudaGetSymbolAddress((void**)&xh,  g_xh);
    cudaGetSymbolAddress((void**)&wqk, g_Wqk);
    cudaGetSymbolAddress((void**)&wv,  g_Wv);
    cudaGetSymbolAddress((void**)&QK,  g_QK);
    cudaGetSymbolAddress((void**)&Vt,  g_Vt);
    cudaGetSymbolAddress((void**)&Sc,  g_Sc);
    cudaGetSymbolAddress((void**)&At,  g_At);

    cudaFuncSetAttribute(gemm_h16_nt<true>,
                         cudaFuncAttributeMaxDynamicSharedMemorySize, SMEM_BYTES);
    cudaFuncSetAttribute(gemm_h16_nt<false>,
                         cudaFuncAttributeMaxDynamicSharedMemorySize, SMEM_BYTES);

    // 0) convert inputs to fp16 (each block: 2048 floats)
    {
        const int nx = NB * SEQ * DIN;      // 8388608 -> 4096 blocks
        const int nw = DH * DIN;            // 1048576 -> 512 blocks
        cvt_h_kernel<<<nx / 2048, 256>>>((const float4*)x,  (uint4*)xh);
        cvt_h_kernel<<<nw / 2048, 256>>>((const float4*)Wq, (uint4*)wqk);
        cvt_h_kernel<<<nw / 2048, 256>>>((const float4*)Wk,
                                         (uint4*)(wqk + (size_t)DH * DIN));
        cvt_h_kernel<<<nw / 2048, 256>>>((const float4*)Wv, (uint4*)wv);
    }

    // 1) [Q|K] = xh @ [Wq;Wk]^T : one GEMM, N = 2*DH, fp16 out
    {
        dim3 grid((2 * DH) / BN, (NB * SEQ) / BM, 1);     // (16, 64)
        gemm_h16_nt<true><<<grid, 256, SMEM_BYTES>>>(xh, wqk, QK, DIN,
                                                     DIN, DIN, 2 * DH, 1.0f,
                                                     0, 0, 0);
    }

    // 2) V^T_b = Wv @ x_b^T : M=DH, N=SEQ, K=DIN (per batch), fp16 out
    {
        dim3 grid(SEQ / BN, DH / BM, NB);                 // (16, 8, 4)
        gemm_h16_nt<true><<<grid, 256, SMEM_BYTES>>>(wv, xh, Vt, DIN,
                                                     DIN, DIN, SEQ, 1.0f,
                                                     0, (size_t)SEQ * DIN,
                                                     (size_t)DH * SEQ);
    }

    // 3) scores_b = (Q_b @ K_b^T) / sqrt(SEQ), fp32 out
    {
        const float scale = 1.0f / sqrtf((float)SEQ);
        dim3 grid(SEQ / BN, SEQ / BM, NB);                // (16, 16, 4)
        gemm_h16_nt<false><<<grid, 256, SMEM_BYTES>>>(QK, QK + DH, Sc, DH,
                                                      2 * DH, 2 * DH, SEQ, scale,
                                                      (size_t)SEQ * 2 * DH,
                                                      (size_t)SEQ * 2 * DH,
                                                      (size_t)SEQ * SEQ);
    }

    // 4) softmax: fp32 scores -> fp16 attn
    softmax_kernel<<<NB * SEQ, 256>>>(Sc, At);

    // 5) out_b = attn_b @ (V^T_b)^T : M=SEQ, N=DH, K=SEQ, fp32 out
    {
        dim3 grid(DH / BN, SEQ / BM, NB);                 // (8, 16, 4)
        gemm_h16_nt<false><<<grid, 256, SMEM_BYTES>>>(At, Vt, out, SEQ,
                                                      SEQ, SEQ, DH, 1.0f,
                                                      (size_t)SEQ * SEQ,
                                                      (size_t)DH * SEQ,
                                                      (size_t)SEQ * DH);
    }
}

// round 7
// speedup vs baseline: 8.4562x; 1.1304x over previous
#include <cuda_runtime.h>
#include <cuda_fp16.h>
#include <cstdint>
#include <math.h>

// Problem shape (fixed)
#define NB   4
#define SEQ  2048
#define DIN  1024
#define DH   1024

// ---------------------------------------------------------------------------
// Scratch (__device__ globals; no allocs allowed)
// ---------------------------------------------------------------------------
__device__ __half g_xh [(size_t)NB * SEQ * DIN];      // fp16 x            (16 MB)
__device__ __half g_Wqk[(size_t)2 * DH * DIN];        // [Wq; Wk] fp16     (4 MB)
__device__ __half g_Wv [(size_t)DH * DIN];            // fp16              (2 MB)
__device__ __half g_QK [(size_t)NB * SEQ * 2 * DH];   // [Q | K] fp16      (32 MB)
__device__ __half g_Vt [(size_t)NB * DH * SEQ];       // V^T fp16          (16 MB)
__device__ float  g_Sc [(size_t)NB * SEQ * SEQ];      // scores fp32       (64 MB)
__device__ __half g_At [(size_t)NB * SEQ * SEQ];      // attn fp16         (32 MB)

// ---------------------------------------------------------------------------
__device__ __forceinline__ uint32_t smem_u32(const void* p) {
    uint32_t a;
    asm("{ .reg .u64 t; cvta.to.shared.u64 t, %1; cvt.u32.u64 %0, t; }"
        : "=r"(a) : "l"(p));
    return a;
}

#define LDMATRIX_X4(r0, r1, r2, r3, addr)                                      \
    asm volatile("ldmatrix.sync.aligned.m8n8.x4.shared.b16 {%0,%1,%2,%3}, [%4];" \
                 : "=r"(r0), "=r"(r1), "=r"(r2), "=r"(r3) : "r"(addr))

// ---------------------------------------------------------------------------
// fp16 m16n8k16 NT GEMM:  C = alpha * A @ B^T
//   A:[M,K] ldA halfs, B:[N,K] ldB halfs (both K-contiguous), fp32 accum.
//   Tile 128x128x64, 8 warps (64x32 warp tile), 3-stage cp.async, XOR swizzle,
//   ldmatrix.x4 fragment loads. OUT_HALF: C is __half else float.
// ---------------------------------------------------------------------------
constexpr int BM = 128, BN = 128, BK = 64, NST = 3;
constexpr int TILE_H  = BM * BK;                 // 8192 halfs = 16 KB per operand
constexpr int STAGE_H = 2 * TILE_H;              // 32 KB per stage
constexpr int SMEM_BYTES = NST * STAGE_H * 2;    // 98304 B

template <bool OUT_HALF>
__global__ __launch_bounds__(256, 2)
void gemm_h16_nt(const __half* __restrict__ A, const __half* __restrict__ B,
                 void* __restrict__ Cv, int K,
                 int ldA, int ldB, int ldC, float alpha,
                 size_t sA, size_t sB, size_t sC)
{
    extern __shared__ __align__(16) __half sm[];

    const int tid  = threadIdx.x;
    const int wid  = tid >> 5;
    const int lane = tid & 31;
    const int g    = lane >> 2;      // 0..7
    const int tig  = lane & 3;       // 0..3

    const int wm = wid >> 2;         // 0..1 : 64-row warp slab
    const int wn = wid & 3;          // 0..3 : 32-col warp slab

    const __half* Ab = A + sA * blockIdx.z;
    const __half* Bb = B + sB * blockIdx.z;
    const int bm = blockIdx.y * BM;
    const int bn = blockIdx.x * BN;
    const int KT = K / BK;

    const uint32_t smem_base = smem_u32(sm);

    // ldmatrix per-lane row/chunk-select precompute (row&7 == lane&7 always,
    // since all row-base terms are multiples of 8).
    const int xorv = lane & 7;
    // A x4: matrices (rows r..r+7,c0),(r+8..r+15,c0),(r..r+7,c1),(r+8..,c1)
    const int rowA = wm * 64 + (lane & 7) + ((lane >> 3) & 1) * 8;
    const int selA = lane >> 4;                   // 0:c0 1:c1
    // B x4: matrices (rb..rb+7,c0),(rb..,c1),(rb+8..,c0),(rb+8..,c1)
    const int rowB = wn * 32 + (lane & 7) + ((lane >> 4) & 1) * 8;
    const int selB = (lane >> 3) & 1;             // 0:c0 1:c1

    // Stage loader: per operand 128 rows x 64 halfs (128 B) = 8 x 16B chunks.
    // Chunk c of row r stored at physical chunk c ^ (r & 7).
#define LOAD_STAGE(s) do {                                                     \
        const uint32_t _base = smem_base + (uint32_t)(((s) % NST) * STAGE_H * 2); \
        const uint32_t _bB   = _base + (uint32_t)(TILE_H * 2);                 \
        _Pragma("unroll")                                                      \
        for (int _i = 0; _i < 4; _i++) {                                       \
            const int _idx = _i * 256 + tid;                                   \
            const int _row = _idx >> 3;                                        \
            const int _seg = _idx & 7;                                         \
            const uint32_t _soff = (uint32_t)(_row * 128 +                     \
                                   ((_seg ^ (_row & 7)) << 4));                \
            const __half* _ga = Ab + (size_t)(bm + _row) * ldA + (s) * BK + _seg * 8; \
            const __half* _gb = Bb + (size_t)(bn + _row) * ldB + (s) * BK + _seg * 8; \
            asm volatile("cp.async.cg.shared.global [%0], [%1], 16;"           \
                         :: "r"(_base + _soff), "l"(_ga));                     \
            asm volatile("cp.async.cg.shared.global [%0], [%1], 16;"           \
                         :: "r"(_bB + _soff), "l"(_gb));                       \
        }                                                                      \
        asm volatile("cp.async.commit_group;" ::: "memory");                   \
    } while (0)

    float acc[4][4][4];
    #pragma unroll
    for (int i = 0; i < 4; i++)
        #pragma unroll
        for (int j = 0; j < 4; j++)
            #pragma unroll
            for (int r = 0; r < 4; r++) acc[i][j][r] = 0.0f;

    LOAD_STAGE(0);
    LOAD_STAGE(1);

    for (int k0 = 0; k0 < KT; k0++) {
        if (k0 + 1 < KT) asm volatile("cp.async.wait_group 1;" ::: "memory");
        else             asm volatile("cp.async.wait_group 0;" ::: "memory");
        __syncthreads();

        if (k0 + 2 < KT) LOAD_STAGE(k0 + 2);

        const uint32_t stA = smem_base + (uint32_t)((k0 % NST) * STAGE_H * 2);
        const uint32_t stB = stA + (uint32_t)(TILE_H * 2);
        const uint32_t aRowAddr = stA + (uint32_t)(rowA * 128);
        const uint32_t bRowAddr = stB + (uint32_t)(rowB * 128);

        #pragma unroll
        for (int ks = 0; ks < BK / 16; ks++) {
            const uint32_t offA = (uint32_t)(((2 * ks + selA) ^ xorv) << 4);
            const uint32_t offB = (uint32_t)(((2 * ks + selB) ^ xorv) << 4);
            uint32_t a[4][4], b[4][2];
            #pragma unroll
            for (int mf = 0; mf < 4; mf++)
                LDMATRIX_X4(a[mf][0], a[mf][1], a[mf][2], a[mf][3],
                            aRowAddr + (uint32_t)(mf * 16 * 128) + offA);
            #pragma unroll
            for (int p = 0; p < 2; p++)
                LDMATRIX_X4(b[2 * p][0], b[2 * p][1], b[2 * p + 1][0], b[2 * p + 1][1],
                            bRowAddr + (uint32_t)(p * 16 * 128) + offB);
            #pragma unroll
            for (int mf = 0; mf < 4; mf++)
                #pragma unroll
                for (int nf = 0; nf < 4; nf++)
                    asm volatile(
                        "mma.sync.aligned.m16n8k16.row.col.f32.f16.f16.f32 "
                        "{%0,%1,%2,%3}, {%4,%5,%6,%7}, {%8,%9}, {%0,%1,%2,%3};"
                        : "+f"(acc[mf][nf][0]), "+f"(acc[mf][nf][1]),
                          "+f"(acc[mf][nf][2]), "+f"(acc[mf][nf][3])
                        : "r"(a[mf][0]), "r"(a[mf][1]), "r"(a[mf][2]), "r"(a[mf][3]),
                          "r"(b[nf][0]), "r"(b[nf][1]));
        }
    }
#undef LOAD_STAGE

    // Epilogue
    const int mBase = bm + wm * 64 + g;
    const int nBase = bn + wn * 32 + 2 * tig;
    #pragma unroll
    for (int mf = 0; mf < 4; mf++) {
        #pragma unroll
        for (int nf = 0; nf < 4; nf++) {
            const float v0 = acc[mf][nf][0] * alpha, v1 = acc[mf][nf][1] * alpha;
            const float v2 = acc[mf][nf][2] * alpha, v3 = acc[mf][nf][3] * alpha;
            const size_t r0 = (size_t)(mBase + mf * 16) * ldC + nBase + nf * 8;
            const size_t r1 = r0 + 8 * (size_t)ldC;
            if (OUT_HALF) {
                __half* Ch = (__half*)Cv + sC * blockIdx.z;
                *reinterpret_cast<__half2*>(&Ch[r0]) =
                    __float22half2_rn(make_float2(v0, v1));
                *reinterpret_cast<__half2*>(&Ch[r1]) =
                    __float22half2_rn(make_float2(v2, v3));
            } else {
                float* Cf = (float*)Cv + sC * blockIdx.z;
                *reinterpret_cast<float2*>(&Cf[r0]) = make_float2(v0, v1);
                *reinterpret_cast<float2*>(&Cf[r1]) = make_float2(v2, v3);
            }
        }
    }
}

// ---------------------------------------------------------------------------
// Fused fp32 -> fp16 convert for x, Wq, Wk, Wv in ONE launch.
// Each thread: 8 floats (2x float4 -> 1x uint4).
// Block map: [0, 4096) -> x ; [4096, 4608) -> Wq ; [4608, 5120) -> Wk ;
//            [5120, 5632) -> Wv.
// ---------------------------------------------------------------------------
__global__ __launch_bounds__(256)
void cvt_all_kernel(const float4* __restrict__ x,  uint4* __restrict__ xh,
                    const float4* __restrict__ wq, const float4* __restrict__ wk,
                    uint4* __restrict__ wqk,
                    const float4* __restrict__ wv, uint4* __restrict__ wvh)
{
    const int b = blockIdx.x;
    const float4* src;
    uint4* dst;
    int off;
    if (b < 4096)      { src = x;  dst = xh;  off = b; }
    else if (b < 4608) { src = wq; dst = wqk; off = b - 4096; }
    else if (b < 5120) { src = wk; dst = wqk + (size_t)(DH * DIN) / 8; off = b - 4608; }
    else               { src = wv; dst = wvh; off = b - 5120; }

    const int i = off * 256 + threadIdx.x;
    const float4 u = src[2 * i], v = src[2 * i + 1];
    __half2 h0 = __float22half2_rn(make_float2(u.x, u.y));
    __half2 h1 = __float22half2_rn(make_float2(u.z, u.w));
    __half2 h2 = __float22half2_rn(make_float2(v.x, v.y));
    __half2 h3 = __float22half2_rn(make_float2(v.z, v.w));
    uint4 o;
    o.x = *reinterpret_cast<uint32_t*>(&h0);
    o.y = *reinterpret_cast<uint32_t*>(&h1);
    o.z = *reinterpret_cast<uint32_t*>(&h2);
    o.w = *reinterpret_cast<uint32_t*>(&h3);
    dst[i] = o;
}

// ---------------------------------------------------------------------------
// Row softmax: read fp32 scores, write fp16 attn.
// ---------------------------------------------------------------------------
__global__ __launch_bounds__(256)
void softmax_kernel(const float* __restrict__ S, __half* __restrict__ P)
{
    const float* row = S + (size_t)blockIdx.x * SEQ;
    __half*     orow = P + (size_t)blockIdx.x * SEQ;
    const int tid  = threadIdx.x;
    const int lane = tid & 31;
    const int warp = tid >> 5;

    float4 v0 = reinterpret_cast<const float4*>(row)[2 * tid];
    float4 v1 = reinterpret_cast<const float4*>(row)[2 * tid + 1];

    __shared__ float red[8];

    float m = fmaxf(fmaxf(fmaxf(v0.x, v0.y), fmaxf(v0.z, v0.w)),
                    fmaxf(fmaxf(v1.x, v1.y), fmaxf(v1.z, v1.w)));
    #pragma unroll
    for (int o = 16; o > 0; o >>= 1) m = fmaxf(m, __shfl_xor_sync(0xFFFFFFFFu, m, o));
    if (lane == 0) red[warp] = m;
    __syncthreads();
    m = red[0];
    #pragma unroll
    for (int w = 1; w < 8; w++) m = fmaxf(m, red[w]);
    __syncthreads();

    v0.x = __expf(v0.x - m); v0.y = __expf(v0.y - m);
    v0.z = __expf(v0.z - m); v0.w = __expf(v0.w - m);
    v1.x = __expf(v1.x - m); v1.y = __expf(v1.y - m);
    v1.z = __expf(v1.z - m); v1.w = __expf(v1.w - m);

    float s = (v0.x + v0.y + v0.z + v0.w) + (v1.x + v1.y + v1.z + v1.w);
    #pragma unroll
    for (int o = 16; o > 0; o >>= 1) s += __shfl_xor_sync(0xFFFFFFFFu, s, o);
    if (lane == 0) red[warp] = s;
    __syncthreads();
    s = red[0];
    #pragma unroll
    for (int w = 1; w < 8; w++) s += red[w];

    const float inv = 1.0f / s;
    __half2 h0 = __float22half2_rn(make_float2(v0.x * inv, v0.y * inv));
    __half2 h1 = __float22half2_rn(make_float2(v0.z * inv, v0.w * inv));
    __half2 h2 = __float22half2_rn(make_float2(v1.x * inv, v1.y * inv));
    __half2 h3 = __float22half2_rn(make_float2(v1.z * inv, v1.w * inv));
    uint4 o;
    o.x = *reinterpret_cast<uint32_t*>(&h0);
    o.y = *reinterpret_cast<uint32_t*>(&h1);
    o.z = *reinterpret_cast<uint32_t*>(&h2);
    o.w = *reinterpret_cast<uint32_t*>(&h3);
    reinterpret_cast<uint4*>(orow)[tid] = o;
}

// ---------------------------------------------------------------------------
extern "C" void kernel_launch(void* const* d_in, const int* in_sizes, int n_in,
                              void* d_out, int out_size)
{
    (void)in_sizes; (void)n_in; (void)out_size;

    const float* x  = (const float*)d_in[0];
    const float* Wq = (const float*)d_in[1];
    const float* Wk = (const float*)d_in[2];
    const float* Wv = (const float*)d_in[3];
    float*       out = (float*)d_out;

    __half *xh, *wqk, *wv, *QK, *Vt, *At;
    float *Sc;
    cudaGetSymbolAddress((void**)&xh,  g_xh);
    cudaGetSymbolAddress((void**)&wqk, g_Wqk);
    cudaGetSymbolAddress((void**)&wv,  g_Wv);
    cudaGetSymbolAddress((void**)&QK,  g_QK);
    cudaGetSymbolAddress((void**)&Vt,  g_Vt);
    cudaGetSymbolAddress((void**)&Sc,  g_Sc);
    cudaGetSymbolAddress((void**)&At,  g_At);

    cudaFuncSetAttribute(gemm_h16_nt<true>,
                         cudaFuncAttributeMaxDynamicSharedMemorySize, SMEM_BYTES);
    cudaFuncSetAttribute(gemm_h16_nt<false>,
                         cudaFuncAttributeMaxDynamicSharedMemorySize, SMEM_BYTES);

    // 0) convert all inputs to fp16, one launch
    cvt_all_kernel<<<5632, 256>>>((const float4*)x,  (uint4*)xh,
                                  (const float4*)Wq, (const float4*)Wk,
                                  (uint4*)wqk,
                                  (const float4*)Wv, (uint4*)wv);

    // 1) [Q|K] = xh @ [Wq;Wk]^T : one GEMM, N = 2*DH, fp16 out
    {
        dim3 grid((2 * DH) / BN, (NB * SEQ) / BM, 1);     // (16, 64)
        gemm_h16_nt<true><<<grid, 256, SMEM_BYTES>>>(xh, wqk, QK, DIN,
                                                     DIN, DIN, 2 * DH, 1.0f,
                                                     0, 0, 0);
    }

    // 2) V^T_b = Wv @ x_b^T : M=DH, N=SEQ, K=DIN (per batch), fp16 out
    {
        dim3 grid(SEQ / BN, DH / BM, NB);                 // (16, 8, 4)
        gemm_h16_nt<true><<<grid, 256, SMEM_BYTES>>>(wv, xh, Vt, DIN,
                                                     DIN, DIN, SEQ, 1.0f,
                                                     0, (size_t)SEQ * DIN,
                                                     (size_t)DH * SEQ);
    }

    // 3) scores_b = (Q_b @ K_b^T) / sqrt(SEQ), fp32 out
    {
        const float scale = 1.0f / sqrtf((float)SEQ);
        dim3 grid(SEQ / BN, SEQ / BM, NB);                // (16, 16, 4)
        gemm_h16_nt<false><<<grid, 256, SMEM_BYTES>>>(QK, QK + DH, Sc, DH,
                                                      2 * DH, 2 * DH, SEQ, scale,
                                                      (size_t)SEQ * 2 * DH,
                                                      (size_t)SEQ * 2 * DH,
                                                      (size_t)SEQ * SEQ);
    }

    // 4) softmax: fp32 scores -> fp16 attn
    softmax_kernel<<<NB * SEQ, 256>>>(Sc, At);

    // 5) out_b = attn_b @ (V^T_b)^T : M=SEQ, N=DH, K=SEQ, fp32 out
    {
        dim3 grid(DH / BN, SEQ / BM, NB);                 // (8, 16, 4)
        gemm_h16_nt<false><<<grid, 256, SMEM_BYTES>>>(At, Vt, out, SEQ,
                                                      SEQ, SEQ, DH, 1.0f,
                                                      (size_t)SEQ * SEQ,
                                                      (size_t)DH * SEQ,
                                                      (size_t)SEQ * DH);
    }
}